// round 5
// baseline (speedup 1.0000x reference)
#include <cuda_runtime.h>
#include <float.h>
#include <math.h>

#define A_  64
#define B_  256
#define L_  2000
#define FC1 32     // conv1 out channels
#define FC2 64     // conv2 out channels
#define H_  128
#define KK  5
#define TILE 128
#define NTILE 16   // 16*128 = 2048 >= 2000
#define NTHR 512

typedef unsigned long long u64;

// ---------------- scratch (device globals; no allocation allowed) ----------
__device__ float g_U[B_ * L_ * A_];          // u[b][l][a], 131 MB
__device__ float g_pmax[B_ * NTILE * A_];    // per-tile max   [b][tile][a]
__device__ float g_psum[B_ * NTILE * A_];    // per-tile sumexp[b][tile][a]
__device__ float g_logZ[B_ * A_];            // logsumexp over l, [b][a]

// ---------------- shared memory layout (bytes) ------------------------------
#define SM_C2S   0                 // float[64][128]        32768
#define SM_HS    32768             // float[128][128]       65536 (aliased by conv bufs)
#define SM_WBUF  98304             // 16384 floats          65536 (w1dup / w2s / diffdup)
#define SM_RED   163840            // float[32][64]          8192
#define SM_BM    172032            // float[64]               256
#define SM_TOTAL 172288
// conv-phase aliases inside [SM_HS, SM_WBUF):
#define SM_BINC  (SM_HS)                       // 136 floats (544 B)
#define SM_C1    (SM_HS + 544)                 // float[32][132] (16896 B)
#define SM_C2W   (SM_C1 + 32*132*4)            // float2[32*32*5] (40960 B)
#define SM_C1W   (SM_C2W + 5120*8)             // 160 floats
#define SM_C1B   (SM_C1W + 160*4)              // 32 floats
#define SM_C2B   (SM_C1B + 32*4)               // 64 floats

// ---- packed f32x2 helpers ----
__device__ __forceinline__ u64 pk2(float x) {
    u64 r; asm("mov.b64 %0, {%1, %1};" : "=l"(r) : "f"(x)); return r;
}
__device__ __forceinline__ u64 pk2two(float x, float y) {
    u64 r; asm("mov.b64 %0, {%1, %2};" : "=l"(r) : "f"(x), "f"(y)); return r;
}
__device__ __forceinline__ void fma2(u64& d, u64 a, u64 b) {
    asm("fma.rn.f32x2 %0, %1, %2, %0;" : "+l"(d) : "l"(a), "l"(b));
}
__device__ __forceinline__ float2 up(u64 v) {
    float2 f; asm("mov.b64 {%0, %1}, %2;" : "=f"(f.x), "=f"(f.y) : "l"(v)); return f;
}

__global__ void __launch_bounds__(NTHR, 1)
fused_kernel(const float* __restrict__ binc_g,
             const float* __restrict__ c1w_g, const float* __restrict__ c1b_g,
             const float* __restrict__ c2w_g, const float* __restrict__ c2b_g,
             const float* __restrict__ l1w_g, const float* __restrict__ l1b_g,
             const float* __restrict__ l2w_g, const float* __restrict__ l2b_g,
             const float* __restrict__ baseline_g,
             const float* __restrict__ diff_g,
             const int*   __restrict__ regions_oi_g)
{
    extern __shared__ char smem[];
    float* c2s   = (float*)(smem + SM_C2S);    // [64][128]  (oc, l)
    float* hs    = (float*)(smem + SM_HS);     // [128][128] (feat, l)
    float* wbuf  = (float*)(smem + SM_WBUF);   // 16384 floats, phase-dependent layout
    float* red   = (float*)(smem + SM_RED);    // [32][64]
    float* bm    = (float*)(smem + SM_BM);     // [64]
    float* sbinc = (float*)(smem + SM_BINC);
    float* sc1   = (float*)(smem + SM_C1);     // [32][132]
    u64*   sc2wp = (u64*)(smem + SM_C2W);      // float2-packed conv2 weights (oc-pairs)
    float* sc1w  = (float*)(smem + SM_C1W);
    float* sc1b  = (float*)(smem + SM_C1B);
    float* sc2b  = (float*)(smem + SM_C2B);

    const int t       = threadIdx.x;
    const int tileIdx = blockIdx.x;
    const int b       = blockIdx.y;
    const int l0      = tileIdx * TILE;

    // ---- stage conv weights (oc-pair interleaved) + w1 duplicated ----
    // sc2wp[(op*32+ic)*5+k] = {w[2op][ic][k], w[2op+1][ic][k]}
    for (int i = t; i < 32 * 32 * 5; i += NTHR) {
        int op  = i / 160;
        int rem = i - op * 160;
        int ic  = rem / 5;
        int k   = rem - ic * 5;
        float w0 = c2w_g[(op * 64 + ic) * 5 + k];
        float w1 = c2w_g[(op * 64 + 32 + ic) * 5 + k];
        ((float2*)sc2wp)[i] = make_float2(w0, w1);
    }
    if (t < FC1 * KK) sc1w[t] = c1w_g[t];
    if (t < FC1)      sc1b[t] = c1b_g[t];
    if (t < FC2)      sc2b[t] = c2b_g[t];
    // w1 duplicated, tx-major: j = tx*8 + jg*2 + p  ->
    //   wbuf[(k*4+jg)*64 + tx*4 + p*2 + {0,1}] = w1[j][k]   (lin1_w is [128][64])
    for (int idx = t; idx < 128 * 64; idx += NTHR) {
        int j = idx >> 6, k = idx & 63;
        float v = l1w_g[idx];
        int jg = (j >> 1) & 3, txw = j >> 3, p = j & 1;
        int base = (k * 4 + jg) * 64 + txw * 4 + p * 2;
        wbuf[base] = v; wbuf[base + 1] = v;
    }
    // bincounts halo slice: global l in [l0-4, l0+132)
    if (t < TILE + 8) {
        int l = l0 - 4 + t;
        sbinc[t] = (l >= 0 && l < L_) ? binc_g[b * L_ + l] : 0.f;
    }
    __syncthreads();

    // ---- conv1: sc1[ic][j], j in [0,132) <-> l = l0-2+j; halo masked to 0 ----
    for (int idx = t; idx < FC1 * 132; idx += NTHR) {
        int ic = idx / 132, j = idx % 132;
        int gl = l0 - 2 + j;
        float acc = sc1b[ic];
        #pragma unroll
        for (int k = 0; k < KK; k++) acc += sbinc[j + k] * sc1w[ic * KK + k];
        sc1[ic * 132 + j] = (gl >= 0 && gl < L_) ? acc : 0.f;
    }
    __syncthreads();

    // ---- conv2 (oc-pair packed f32x2): 512 items = (op, 8-l group), 1/thread ----
    {
        int item = t;  // 32*16 == NTHR
        int op = item >> 4;
        int lb = (item & 15) * 8;
        u64 binit = pk2two(sc2b[2 * op], sc2b[2 * op + 1]);
        u64 acc2[8];
        #pragma unroll
        for (int i = 0; i < 8; i++) acc2[i] = binit;
        for (int ic = 0; ic < FC1; ic++) {
            u64 xv2[12];
            #pragma unroll
            for (int i = 0; i < 12; i++) xv2[i] = pk2(sc1[ic * 132 + lb + i]);
            const u64* wp = &sc2wp[(op * 32 + ic) * 5];
            #pragma unroll
            for (int k = 0; k < KK; k++) {
                u64 w2k = wp[k];
                #pragma unroll
                for (int i = 0; i < 8; i++) fma2(acc2[i], xv2[i + k], w2k);
            }
        }
        #pragma unroll
        for (int i = 0; i < 8; i++) {
            float2 r = up(acc2[i]);
            c2s[(2 * op)     * 128 + lb + i] = r.x;
            c2s[(2 * op + 1) * 128 + lb + i] = r.y;
        }
    }
    __syncthreads();

    // ---- register-tiled GEMMs: 16x32 threads, 4-row x 8-col thread tiles ----
    const int tx = t & 15, ty = t >> 4;   // tx 0..15, ty 0..31
    const int row0 = ty * 4;     // l within tile
    const int col0 = tx * 8;     // output feature

    // GEMM1 (K=64): i-packed. a pairs from one float4; b pre-duplicated in wbuf.
    u64 acc2[2][8];
    #pragma unroll
    for (int i = 0; i < 2; i++)
        #pragma unroll
        for (int j = 0; j < 8; j++) acc2[i][j] = 0ull;
    for (int k = 0; k < 64; k++) {
        ulonglong2 A0 = *(const ulonglong2*)&c2s[k * 128 + row0];
        u64 av2[2] = {A0.x, A0.y};
        u64 bv2[8];
        #pragma unroll
        for (int jg = 0; jg < 4; jg++) {
            ulonglong2 Bg = *(const ulonglong2*)&wbuf[(k * 4 + jg) * 64 + tx * 4];
            bv2[jg * 2] = Bg.x; bv2[jg * 2 + 1] = Bg.y;
        }
        #pragma unroll
        for (int i = 0; i < 2; i++)
            #pragma unroll
            for (int j = 0; j < 8; j++) fma2(acc2[i][j], av2[i], bv2[j]);
    }
    __syncthreads();   // all k-loop reads of c2s/wbuf finished

    // epilogue: hs[j][l] = relu(acc + b1[j]); stage w2 (tx-major) into wbuf
    {
        #pragma unroll
        for (int j = 0; j < 8; j++) {
            float bj = l1b_g[col0 + j];
            #pragma unroll
            for (int i = 0; i < 2; i++) {
                float2 v = up(acc2[i][j]);
                hs[(col0 + j) * 128 + row0 + 2 * i]     = fmaxf(v.x + bj, 0.f);
                hs[(col0 + j) * 128 + row0 + 2 * i + 1] = fmaxf(v.y + bj, 0.f);
            }
        }
    }
    // w2 tx-major: j = tx*8 + jg*4 + jj -> wbuf[(k*2+jg)*64 + tx*4 + jj]
    for (int idx = t; idx < 128 * 128; idx += NTHR) {
        int j = idx >> 7, k = idx & 127;
        int jg = (j >> 2) & 1, txw = j >> 3, jj = j & 3;
        wbuf[(k * 2 + jg) * 64 + txw * 4 + jj] = l2w_g[idx];
    }
    __syncthreads();

    // GEMM2 (K=128): j-packed. b pairs aligned from float4; a replicated.
    u64 accB[4][4];
    #pragma unroll
    for (int i = 0; i < 4; i++)
        #pragma unroll
        for (int q = 0; q < 4; q++) accB[i][q] = 0ull;
    for (int k = 0; k < 128; k++) {
        float4 a0 = *(const float4*)&hs[k * 128 + row0];
        u64 av2[4] = {pk2(a0.x), pk2(a0.y), pk2(a0.z), pk2(a0.w)};
        ulonglong2 B0 = *(const ulonglong2*)&wbuf[(k * 2 + 0) * 64 + tx * 4];
        ulonglong2 B1 = *(const ulonglong2*)&wbuf[(k * 2 + 1) * 64 + tx * 4];
        u64 bv2[4] = {B0.x, B0.y, B1.x, B1.y};
        #pragma unroll
        for (int i = 0; i < 4; i++)
            #pragma unroll
            for (int q = 0; q < 4; q++) fma2(accB[i][q], av2[i], bv2[q]);
    }
    __syncthreads();

    {
        #pragma unroll
        for (int q = 0; q < 4; q++) {
            float bx = l2b_g[col0 + 2 * q];
            float by = l2b_g[col0 + 2 * q + 1];
            #pragma unroll
            for (int i = 0; i < 4; i++) {
                float2 v = up(accB[i][q]);
                hs[(col0 + 2 * q)     * 128 + row0 + i] = fmaxf(v.x + bx, 0.f);
                hs[(col0 + 2 * q + 1) * 128 + row0 + i] = fmaxf(v.y + by, 0.f);
            }
        }
    }
    // diff duplicated, tx-major: a = tx*4 + jg*2 + p ->
    //   wbuf[(k*2+jg)*64 + tx*4 + p*2 + {0,1}] = diff[a][k]  (differential [64][128])
    for (int idx = t; idx < 64 * 128; idx += NTHR) {
        int a = idx >> 7, k = idx & 127;
        float v = diff_g[idx];
        int jg = (a >> 1) & 1, txw = a >> 2, p = a & 1;
        int base = (k * 2 + jg) * 64 + txw * 4 + p * 2;
        wbuf[base] = v; wbuf[base + 1] = v;
    }
    __syncthreads();

    // GEMM3 (K=128, N=64): i-packed, diff pre-duplicated. acc pairs over l.
    const int col3 = tx * 4;  // a
    u64 accC[2][4];
    #pragma unroll
    for (int i = 0; i < 2; i++)
        #pragma unroll
        for (int j = 0; j < 4; j++) accC[i][j] = 0ull;
    for (int k = 0; k < 128; k++) {
        ulonglong2 A0 = *(const ulonglong2*)&hs[k * 128 + row0];
        u64 av2[2] = {A0.x, A0.y};
        ulonglong2 B0 = *(const ulonglong2*)&wbuf[(k * 2 + 0) * 64 + tx * 4];
        ulonglong2 B1 = *(const ulonglong2*)&wbuf[(k * 2 + 1) * 64 + tx * 4];
        u64 bv2[4] = {B0.x, B0.y, B1.x, B1.y};
        #pragma unroll
        for (int i = 0; i < 2; i++)
            #pragma unroll
            for (int j = 0; j < 4; j++) fma2(accC[i][j], av2[i], bv2[j]);
    }

    // epilogue: add baseline, write u, per-tile logsumexp partials
    const int r = regions_oi_g[b];
    float bval[4];
    bool  valid[4];
    #pragma unroll
    for (int i = 0; i < 4; i++) {
        int gl = l0 + row0 + i;
        valid[i] = (gl < L_);
        bval[i]  = valid[i] ? baseline_g[r * L_ + gl] : 0.f;
    }
    float uv[4][4];
    #pragma unroll
    for (int i2 = 0; i2 < 2; i2++) {
        #pragma unroll
        for (int j = 0; j < 4; j++) {
            float2 v = up(accC[i2][j]);
            uv[2 * i2][j]     = v.x + bval[2 * i2];
            uv[2 * i2 + 1][j] = v.y + bval[2 * i2 + 1];
        }
    }
    float mloc[4] = {-FLT_MAX, -FLT_MAX, -FLT_MAX, -FLT_MAX};
    #pragma unroll
    for (int i = 0; i < 4; i++) {
        if (!valid[i]) continue;
        int gl = l0 + row0 + i;
        *(float4*)&g_U[(size_t)(b * L_ + gl) * A_ + col3] =
            make_float4(uv[i][0], uv[i][1], uv[i][2], uv[i][3]);
        #pragma unroll
        for (int j = 0; j < 4; j++) mloc[j] = fmaxf(mloc[j], uv[i][j]);
    }
    #pragma unroll
    for (int j = 0; j < 4; j++) red[ty * 64 + col3 + j] = mloc[j];
    __syncthreads();
    if (t < 64) {
        float m = -FLT_MAX;
        #pragma unroll
        for (int q = 0; q < 32; q++) m = fmaxf(m, red[q * 64 + t]);
        bm[t] = m;
    }
    __syncthreads();
    float bmj[4];
    #pragma unroll
    for (int j = 0; j < 4; j++) bmj[j] = bm[col3 + j];
    float sloc[4] = {0.f, 0.f, 0.f, 0.f};
    #pragma unroll
    for (int i = 0; i < 4; i++) {
        if (!valid[i]) continue;
        #pragma unroll
        for (int j = 0; j < 4; j++) sloc[j] += __expf(uv[i][j] - bmj[j]);
    }
    #pragma unroll
    for (int j = 0; j < 4; j++) red[ty * 64 + col3 + j] = sloc[j];
    __syncthreads();
    if (t < 64) {
        float s = 0.f;
        #pragma unroll
        for (int q = 0; q < 32; q++) s += red[q * 64 + t];
        g_pmax[(b * NTILE + tileIdx) * A_ + t] = bm[t];
        g_psum[(b * NTILE + tileIdx) * A_ + t] = s;
    }
}

// combine per-tile partials into logZ[b][a]
__global__ void combine_kernel()
{
    int id = blockIdx.x * blockDim.x + threadIdx.x;
    if (id >= B_ * A_) return;
    int b = id >> 6, a = id & 63;
    float m = -FLT_MAX;
    #pragma unroll
    for (int q = 0; q < NTILE; q++)
        m = fmaxf(m, g_pmax[(b * NTILE + q) * A_ + a]);
    float s = 0.f;
    #pragma unroll
    for (int q = 0; q < NTILE; q++)
        s += g_psum[(b * NTILE + q) * A_ + a] * __expf(g_pmax[(b * NTILE + q) * A_ + a] - m);
    g_logZ[b * A_ + a] = m + logf(s);
}

__global__ void gather_kernel(const int* __restrict__ labels,
                              const int* __restrict__ cell_ix,
                              const int* __restrict__ region_ix,
                              const int* __restrict__ binixs,
                              float* __restrict__ out, int nf)
{
    int f = blockIdx.x * blockDim.x + threadIdx.x;
    if (f >= nf) return;
    int a = labels[cell_ix[f]];
    int b = region_ix[f];
    int l = binixs[f];
    out[f] = g_U[(size_t)(b * L_ + l) * A_ + a] - g_logZ[b * A_ + a]
           + 5.545177444479562f;  // + log(B=256)
}

extern "C" void kernel_launch(void* const* d_in, const int* in_sizes, int n_in,
                              void* d_out, int out_size)
{
    const float* bincounts  = (const float*)d_in[0];
    const float* conv1_w    = (const float*)d_in[1];
    const float* conv1_b    = (const float*)d_in[2];
    const float* conv2_w    = (const float*)d_in[3];
    const float* conv2_b    = (const float*)d_in[4];
    const float* lin1_w     = (const float*)d_in[5];
    const float* lin1_b     = (const float*)d_in[6];
    const float* lin2_w     = (const float*)d_in[7];
    const float* lin2_b     = (const float*)d_in[8];
    const float* baseline   = (const float*)d_in[9];
    const float* diff       = (const float*)d_in[10];
    const int*   regions_oi = (const int*)d_in[11];
    const int*   labels     = (const int*)d_in[12];
    const int*   cell_ix    = (const int*)d_in[13];
    const int*   region_ix  = (const int*)d_in[14];
    const int*   binixs     = (const int*)d_in[15];
    float* out = (float*)d_out;
    int nf = in_sizes[13];

    cudaFuncSetAttribute(fused_kernel,
                         cudaFuncAttributeMaxDynamicSharedMemorySize, SM_TOTAL);

    dim3 grid(NTILE, B_);
    fused_kernel<<<grid, NTHR, SM_TOTAL>>>(bincounts, conv1_w, conv1_b,
                                           conv2_w, conv2_b, lin1_w, lin1_b,
                                           lin2_w, lin2_b, baseline, diff,
                                           regions_oi);
    combine_kernel<<<(B_ * A_ + 255) / 256, 256>>>();
    gather_kernel<<<(nf + 255) / 256, 256>>>(labels, cell_ix, region_ix,
                                             binixs, out, nf);
}

// round 6
// speedup vs baseline: 1.7071x; 1.7071x over previous
#include <cuda_runtime.h>
#include <float.h>
#include <math.h>

#define A_  64
#define B_  256
#define L_  2000
#define FC1 32     // conv1 out channels
#define FC2 64     // conv2 out channels
#define H_  128
#define KK  5
#define TILE 128
#define NTILE 16   // 16*128 = 2048 >= 2000
#define NTHR 256

typedef unsigned long long u64;

// ---------------- scratch (device globals; no allocation allowed) ----------
__device__ float g_U[B_ * L_ * A_];          // u[b][l][a], 131 MB
__device__ float g_pmax[B_ * NTILE * A_];    // per-tile max   [b][tile][a]
__device__ float g_psum[B_ * NTILE * A_];    // per-tile sumexp[b][tile][a]
__device__ float g_logZ[B_ * A_];            // logsumexp over l, [b][a]

// pre-transposed weights (filled by init_kernel each launch)
__device__ float  g_w1t[64 * 128];      // [(k*2+h)*64 + tx*4 + jj] = w1[j][k]
__device__ float  g_w2t[128 * 128];     // [(k*2+h)*64 + tx*4 + jj] = w2[j][k]
__device__ float  g_difft[128 * 64];    // [k*64 + a] = diff[a][k]
__device__ float2 g_c2wp[32 * 32 * 5];  // [(op*32+ic)*5+k] = {w[2op][ic][k], w[2op+1][ic][k]}

// ---------------- shared memory layout (bytes) ------------------------------
#define SM_C2S   0                 // float[64][128]        32768
#define SM_HS    32768             // float[128][128]       65536 (aliased by conv bufs)
#define SM_WBUF  98304             // 16384 floats          65536 (w1t / w2t / difft)
#define SM_RED   163840            // float[16][64]          4096
#define SM_BM    167936            // float[64]               256
#define SM_TOTAL 168192
// conv-phase aliases inside [SM_HS, SM_WBUF):
#define SM_BINC  (SM_HS)                       // 136 floats (544 B)
#define SM_C1    (SM_HS + 544)                 // float[32][132] (16896 B)
#define SM_C2W   (SM_C1 + 32*132*4)            // float2[32*32*5] (40960 B)
#define SM_C1W   (SM_C2W + 5120*8)             // 160 floats
#define SM_C1B   (SM_C1W + 160*4)              // 32 floats
#define SM_C2B   (SM_C1B + 32*4)               // 64 floats

// ---- packed f32x2 helpers ----
__device__ __forceinline__ u64 pk2(float x) {
    u64 r; asm("mov.b64 %0, {%1, %1};" : "=l"(r) : "f"(x)); return r;
}
__device__ __forceinline__ u64 pk2two(float x, float y) {
    u64 r; asm("mov.b64 %0, {%1, %2};" : "=l"(r) : "f"(x), "f"(y)); return r;
}
__device__ __forceinline__ void fma2(u64& d, u64 a, u64 b) {
    asm("fma.rn.f32x2 %0, %1, %2, %0;" : "+l"(d) : "l"(a), "l"(b));
}
__device__ __forceinline__ float2 up(u64 v) {
    float2 f; asm("mov.b64 {%0, %1}, %2;" : "=f"(f.x), "=f"(f.y) : "l"(v)); return f;
}

// ---- one-time weight transposition into smem-ready layouts -----------------
__global__ void init_kernel(const float* __restrict__ l1w,
                            const float* __restrict__ l2w,
                            const float* __restrict__ diff,
                            const float* __restrict__ c2w)
{
    int t = blockIdx.x * blockDim.x + threadIdx.x;
    // w1t: j<128, k<64
    if (t < 128 * 64) {
        int j = t >> 6, k = t & 63;
        int h = (j >> 2) & 1, txw = j >> 3, jj = j & 3;
        g_w1t[(k * 2 + h) * 64 + txw * 4 + jj] = l1w[j * 64 + k];
    }
    // w2t: j<128, k<128
    if (t < 128 * 128) {
        int j = t >> 7, k = t & 127;
        int h = (j >> 2) & 1, txw = j >> 3, jj = j & 3;
        g_w2t[(k * 2 + h) * 64 + txw * 4 + jj] = l2w[j * 128 + k];
    }
    // difft: a<64, k<128
    if (t < 64 * 128) {
        int a = t >> 7, k = t & 127;
        g_difft[k * 64 + a] = diff[a * 128 + k];
    }
    // conv2 weights, oc-pair interleaved
    if (t < 32 * 32 * 5) {
        int op  = t / 160;
        int rem = t - op * 160;
        int ic  = rem / 5;
        int k   = rem - ic * 5;
        g_c2wp[t] = make_float2(c2w[(op * 64 + ic) * 5 + k],
                                c2w[(op * 64 + 32 + ic) * 5 + k]);
    }
}

__global__ void __launch_bounds__(NTHR, 1)
fused_kernel(const float* __restrict__ binc_g,
             const float* __restrict__ c1w_g, const float* __restrict__ c1b_g,
             const float* __restrict__ c2b_g,
             const float* __restrict__ l1b_g, const float* __restrict__ l2b_g,
             const float* __restrict__ baseline_g,
             const int*   __restrict__ regions_oi_g)
{
    extern __shared__ char smem[];
    float* c2s   = (float*)(smem + SM_C2S);    // [64][128]  (oc, l)
    float* hs    = (float*)(smem + SM_HS);     // [128][128] (feat, l)
    float* wbuf  = (float*)(smem + SM_WBUF);   // 16384 floats, phase-dependent
    float* red   = (float*)(smem + SM_RED);    // [16][64]
    float* bm    = (float*)(smem + SM_BM);     // [64]
    float* sbinc = (float*)(smem + SM_BINC);
    float* sc1   = (float*)(smem + SM_C1);     // [32][132]
    u64*   sc2wp = (u64*)(smem + SM_C2W);      // float2-packed conv2 weights
    float* sc1w  = (float*)(smem + SM_C1W);
    float* sc1b  = (float*)(smem + SM_C1B);
    float* sc2b  = (float*)(smem + SM_C2B);

    const int t       = threadIdx.x;
    const int tileIdx = blockIdx.x;
    const int b       = blockIdx.y;
    const int l0      = tileIdx * TILE;

    // ---- coalesced staging: conv2 weights + w1t ----
    {
        const float4* s1 = (const float4*)g_c2wp;
        float4*       d1 = (float4*)sc2wp;
        #pragma unroll
        for (int i = 0; i < 10; i++) d1[t + i * NTHR] = s1[t + i * NTHR];
        const float4* s2 = (const float4*)g_w1t;
        float4*       d2 = (float4*)wbuf;
        #pragma unroll
        for (int i = 0; i < 8; i++) d2[t + i * NTHR] = s2[t + i * NTHR];
    }
    if (t < FC1 * KK) sc1w[t] = c1w_g[t];
    if (t < FC1)      sc1b[t] = c1b_g[t];
    if (t < FC2)      sc2b[t] = c2b_g[t];
    // bincounts halo slice: global l in [l0-4, l0+132)
    if (t < TILE + 8) {
        int l = l0 - 4 + t;
        sbinc[t] = (l >= 0 && l < L_) ? binc_g[b * L_ + l] : 0.f;
    }
    __syncthreads();

    // ---- conv1: sc1[ic][j], j in [0,132) <-> l = l0-2+j; halo masked to 0 ----
    for (int idx = t; idx < FC1 * 132; idx += NTHR) {
        int ic = idx / 132, j = idx % 132;
        int gl = l0 - 2 + j;
        float acc = sc1b[ic];
        #pragma unroll
        for (int k = 0; k < KK; k++) acc += sbinc[j + k] * sc1w[ic * KK + k];
        sc1[ic * 132 + j] = (gl >= 0 && gl < L_) ? acc : 0.f;
    }
    __syncthreads();

    // ---- conv2 (oc-pair packed f32x2): 512 items = (op, 8-l group) ----
    for (int item = t; item < 32 * 16; item += NTHR) {
        int op = item >> 4;
        int lb = (item & 15) * 8;
        u64 binit = pk2two(sc2b[2 * op], sc2b[2 * op + 1]);
        u64 acc2[8];
        #pragma unroll
        for (int i = 0; i < 8; i++) acc2[i] = binit;
        for (int ic = 0; ic < FC1; ic++) {
            const float4* sp = (const float4*)&sc1[ic * 132 + lb];  // 16B aligned
            float4 x0 = sp[0], x1 = sp[1], x2 = sp[2];
            float xs[12] = {x0.x, x0.y, x0.z, x0.w, x1.x, x1.y, x1.z, x1.w,
                            x2.x, x2.y, x2.z, x2.w};
            u64 xv2[12];
            #pragma unroll
            for (int i = 0; i < 12; i++) xv2[i] = pk2(xs[i]);
            const u64* wp = &sc2wp[(op * 32 + ic) * 5];
            #pragma unroll
            for (int k = 0; k < KK; k++) {
                u64 w2k = wp[k];
                #pragma unroll
                for (int i = 0; i < 8; i++) fma2(acc2[i], xv2[i + k], w2k);
            }
        }
        #pragma unroll
        for (int i = 0; i < 8; i++) {
            float2 r = up(acc2[i]);
            c2s[(2 * op)     * 128 + lb + i] = r.x;
            c2s[(2 * op + 1) * 128 + lb + i] = r.y;
        }
    }
    __syncthreads();

    // ---- register-tiled GEMMs: 16x16 threads, 8x8 thread tiles, j-packed ----
    const int tx = t & 15, ty = t >> 4;
    const int row0 = ty * 8;     // l within tile
    const int col0 = tx * 8;     // output feature

    // GEMM1 (K=64): j-packed. B pairs adjacent in tx-major halves; A via pk2.
    u64 acc2[8][4];
    #pragma unroll
    for (int i = 0; i < 8; i++)
        #pragma unroll
        for (int p = 0; p < 4; p++) acc2[i][p] = 0ull;
    for (int k = 0; k < 64; k++) {
        float4 a0 = *(const float4*)&c2s[k * 128 + row0];
        float4 a1 = *(const float4*)&c2s[k * 128 + row0 + 4];
        u64 av2[8] = {pk2(a0.x), pk2(a0.y), pk2(a0.z), pk2(a0.w),
                      pk2(a1.x), pk2(a1.y), pk2(a1.z), pk2(a1.w)};
        ulonglong2 B0 = *(const ulonglong2*)&wbuf[(k * 2 + 0) * 64 + tx * 4];
        ulonglong2 B1 = *(const ulonglong2*)&wbuf[(k * 2 + 1) * 64 + tx * 4];
        u64 bv2[4] = {B0.x, B0.y, B1.x, B1.y};
        #pragma unroll
        for (int i = 0; i < 8; i++)
            #pragma unroll
            for (int p = 0; p < 4; p++) fma2(acc2[i][p], av2[i], bv2[p]);
    }
    __syncthreads();   // all k-loop reads of c2s/wbuf finished

    // epilogue: hs[j][l] = relu(acc + b1[j]); stage w2t into wbuf (coalesced)
    {
        #pragma unroll
        for (int p = 0; p < 4; p++) {
            float bx = l1b_g[col0 + 2 * p];
            float by = l1b_g[col0 + 2 * p + 1];
            #pragma unroll
            for (int i = 0; i < 8; i++) {
                float2 v = up(acc2[i][p]);
                hs[(col0 + 2 * p)     * 128 + row0 + i] = fmaxf(v.x + bx, 0.f);
                hs[(col0 + 2 * p + 1) * 128 + row0 + i] = fmaxf(v.y + by, 0.f);
            }
        }
    }
    {
        const float4* s = (const float4*)g_w2t;
        float4*       d = (float4*)wbuf;
        #pragma unroll
        for (int i = 0; i < 16; i++) d[t + i * NTHR] = s[t + i * NTHR];
    }
    __syncthreads();

    // GEMM2 (K=128): j-packed, same structure.
    u64 accB[8][4];
    #pragma unroll
    for (int i = 0; i < 8; i++)
        #pragma unroll
        for (int p = 0; p < 4; p++) accB[i][p] = 0ull;
    for (int k = 0; k < 128; k++) {
        float4 a0 = *(const float4*)&hs[k * 128 + row0];
        float4 a1 = *(const float4*)&hs[k * 128 + row0 + 4];
        u64 av2[8] = {pk2(a0.x), pk2(a0.y), pk2(a0.z), pk2(a0.w),
                      pk2(a1.x), pk2(a1.y), pk2(a1.z), pk2(a1.w)};
        ulonglong2 B0 = *(const ulonglong2*)&wbuf[(k * 2 + 0) * 64 + tx * 4];
        ulonglong2 B1 = *(const ulonglong2*)&wbuf[(k * 2 + 1) * 64 + tx * 4];
        u64 bv2[4] = {B0.x, B0.y, B1.x, B1.y};
        #pragma unroll
        for (int i = 0; i < 8; i++)
            #pragma unroll
            for (int p = 0; p < 4; p++) fma2(accB[i][p], av2[i], bv2[p]);
    }
    __syncthreads();

    {
        #pragma unroll
        for (int p = 0; p < 4; p++) {
            float bx = l2b_g[col0 + 2 * p];
            float by = l2b_g[col0 + 2 * p + 1];
            #pragma unroll
            for (int i = 0; i < 8; i++) {
                float2 v = up(accB[i][p]);
                hs[(col0 + 2 * p)     * 128 + row0 + i] = fmaxf(v.x + bx, 0.f);
                hs[(col0 + 2 * p + 1) * 128 + row0 + i] = fmaxf(v.y + by, 0.f);
            }
        }
    }
    {
        const float4* s = (const float4*)g_difft;
        float4*       d = (float4*)wbuf;
        #pragma unroll
        for (int i = 0; i < 8; i++) d[t + i * NTHR] = s[t + i * NTHR];
    }
    __syncthreads();

    // GEMM3 (K=128, N=64): j-packed, B = difft[k][a] plain transpose.
    const int col3 = tx * 4;  // a
    u64 accC[8][2];
    #pragma unroll
    for (int i = 0; i < 8; i++)
        #pragma unroll
        for (int p = 0; p < 2; p++) accC[i][p] = 0ull;
    for (int k = 0; k < 128; k++) {
        float4 a0 = *(const float4*)&hs[k * 128 + row0];
        float4 a1 = *(const float4*)&hs[k * 128 + row0 + 4];
        u64 av2[8] = {pk2(a0.x), pk2(a0.y), pk2(a0.z), pk2(a0.w),
                      pk2(a1.x), pk2(a1.y), pk2(a1.z), pk2(a1.w)};
        ulonglong2 B0 = *(const ulonglong2*)&wbuf[k * 64 + tx * 4];
        u64 bv2[2] = {B0.x, B0.y};
        #pragma unroll
        for (int i = 0; i < 8; i++)
            #pragma unroll
            for (int p = 0; p < 2; p++) fma2(accC[i][p], av2[i], bv2[p]);
    }

    // epilogue: add baseline, write u, per-tile logsumexp partials
    const int r = regions_oi_g[b];
    float bval[8];
    bool  valid[8];
    #pragma unroll
    for (int i = 0; i < 8; i++) {
        int gl = l0 + row0 + i;
        valid[i] = (gl < L_);
        bval[i]  = valid[i] ? baseline_g[r * L_ + gl] : 0.f;
    }
    float uv[8][4];
    #pragma unroll
    for (int i = 0; i < 8; i++) {
        #pragma unroll
        for (int p = 0; p < 2; p++) {
            float2 v = up(accC[i][p]);
            uv[i][2 * p]     = v.x + bval[i];
            uv[i][2 * p + 1] = v.y + bval[i];
        }
    }
    float mloc[4] = {-FLT_MAX, -FLT_MAX, -FLT_MAX, -FLT_MAX};
    #pragma unroll
    for (int i = 0; i < 8; i++) {
        if (!valid[i]) continue;
        int gl = l0 + row0 + i;
        *(float4*)&g_U[(size_t)(b * L_ + gl) * A_ + col3] =
            make_float4(uv[i][0], uv[i][1], uv[i][2], uv[i][3]);
        #pragma unroll
        for (int j = 0; j < 4; j++) mloc[j] = fmaxf(mloc[j], uv[i][j]);
    }
    #pragma unroll
    for (int j = 0; j < 4; j++) red[ty * 64 + col3 + j] = mloc[j];
    __syncthreads();
    if (t < 64) {
        float m = -FLT_MAX;
        #pragma unroll
        for (int q = 0; q < 16; q++) m = fmaxf(m, red[q * 64 + t]);
        bm[t] = m;
    }
    __syncthreads();
    float bmj[4];
    #pragma unroll
    for (int j = 0; j < 4; j++) bmj[j] = bm[col3 + j];
    float sloc[4] = {0.f, 0.f, 0.f, 0.f};
    #pragma unroll
    for (int i = 0; i < 8; i++) {
        if (!valid[i]) continue;
        #pragma unroll
        for (int j = 0; j < 4; j++) sloc[j] += __expf(uv[i][j] - bmj[j]);
    }
    #pragma unroll
    for (int j = 0; j < 4; j++) red[ty * 64 + col3 + j] = sloc[j];
    __syncthreads();
    if (t < 64) {
        float s = 0.f;
        #pragma unroll
        for (int q = 0; q < 16; q++) s += red[q * 64 + t];
        g_pmax[(b * NTILE + tileIdx) * A_ + t] = bm[t];
        g_psum[(b * NTILE + tileIdx) * A_ + t] = s;
    }
}

// combine per-tile partials into logZ[b][a]
__global__ void combine_kernel()
{
    int id = blockIdx.x * blockDim.x + threadIdx.x;
    if (id >= B_ * A_) return;
    int b = id >> 6, a = id & 63;
    float m = -FLT_MAX;
    #pragma unroll
    for (int q = 0; q < NTILE; q++)
        m = fmaxf(m, g_pmax[(b * NTILE + q) * A_ + a]);
    float s = 0.f;
    #pragma unroll
    for (int q = 0; q < NTILE; q++)
        s += g_psum[(b * NTILE + q) * A_ + a] * __expf(g_pmax[(b * NTILE + q) * A_ + a] - m);
    g_logZ[b * A_ + a] = m + logf(s);
}

__global__ void gather_kernel(const int* __restrict__ labels,
                              const int* __restrict__ cell_ix,
                              const int* __restrict__ region_ix,
                              const int* __restrict__ binixs,
                              float* __restrict__ out, int nf)
{
    int f = blockIdx.x * blockDim.x + threadIdx.x;
    if (f >= nf) return;
    int a = labels[cell_ix[f]];
    int b = region_ix[f];
    int l = binixs[f];
    out[f] = g_U[(size_t)(b * L_ + l) * A_ + a] - g_logZ[b * A_ + a]
           + 5.545177444479562f;  // + log(B=256)
}

extern "C" void kernel_launch(void* const* d_in, const int* in_sizes, int n_in,
                              void* d_out, int out_size)
{
    const float* bincounts  = (const float*)d_in[0];
    const float* conv1_w    = (const float*)d_in[1];
    const float* conv1_b    = (const float*)d_in[2];
    const float* conv2_w    = (const float*)d_in[3];
    const float* conv2_b    = (const float*)d_in[4];
    const float* lin1_w     = (const float*)d_in[5];
    const float* lin1_b     = (const float*)d_in[6];
    const float* lin2_w     = (const float*)d_in[7];
    const float* lin2_b     = (const float*)d_in[8];
    const float* baseline   = (const float*)d_in[9];
    const float* diff       = (const float*)d_in[10];
    const int*   regions_oi = (const int*)d_in[11];
    const int*   labels     = (const int*)d_in[12];
    const int*   cell_ix    = (const int*)d_in[13];
    const int*   region_ix  = (const int*)d_in[14];
    const int*   binixs     = (const int*)d_in[15];
    float* out = (float*)d_out;
    int nf = in_sizes[13];

    cudaFuncSetAttribute(fused_kernel,
                         cudaFuncAttributeMaxDynamicSharedMemorySize, SM_TOTAL);

    init_kernel<<<64, 256>>>(lin1_w, lin2_w, diff, conv2_w);

    dim3 grid(NTILE, B_);
    fused_kernel<<<grid, NTHR, SM_TOTAL>>>(bincounts, conv1_w, conv1_b,
                                           conv2_b, lin1_b, lin2_b,
                                           baseline, regions_oi);
    combine_kernel<<<(B_ * A_ + 255) / 256, 256>>>();
    gather_kernel<<<(nf + 255) / 256, 256>>>(labels, cell_ix, region_ix,
                                             binixs, out, nf);
}

// round 7
// speedup vs baseline: 2.4697x; 1.4467x over previous
#include <cuda_runtime.h>
#include <float.h>
#include <math.h>

#define A_  64
#define B_  256
#define L_  2000
#define FC1 32
#define FC2 64
#define H_  128
#define KK  5
#define TILE 128
#define NTILE 16   // 16*128 = 2048 >= 2000
#define NTHR 256

typedef unsigned long long u64;

// ---------------- scratch (device globals; no allocation allowed) ----------
__device__ float g_U[B_ * L_ * A_];          // u[b][l][a], 131 MB
__device__ float g_pmax[B_ * NTILE * A_];
__device__ float g_psum[B_ * NTILE * A_];
__device__ float g_logZ[B_ * A_];

// folded weights (filled by init kernels each launch)
__device__ float  g_WC[64 * 9];          // conv2∘conv1 composite [oc][t], t=k1+k2
__device__ float  g_bC[64];              // composite conv bias (interior)
__device__ float2 g_we9[64 * 9];         // lin1∘conv composite, jp-paired: {WE[2jp][t], WE[2jp+1][t]}
__device__ float2 g_bep[64];             // folded bias pairs {bE[2jp], bE[2jp+1]}
__device__ float  g_w2t[128 * 128];      // [(k*2+h)*64 + txw*4 + jj] = w2[j][k]
__device__ float  g_difft[128 * 64];     // [k*64 + a] = diff[a][k]
__device__ float  g_hsb[B_ * 4 * 128];   // exact boundary h1 (relu'd): [b][li][j], li: l=0,1,L-2,L-1

// ---------------- shared memory layout (bytes) ------------------------------
#define SM_BINC  0                 // 144 floats (576 B)
#define SM_WE9   576               // u64[576] = 4608 B
#define SM_BEP   5184              // float2[64] = 512 B
#define SM_RED   5696              // float[16][64] = 4096 B
#define SM_BM    9792              // float[64] = 256 B
#define SM_HS    32768             // float[128][128] = 65536
#define SM_WBUF  98304             // 16384 floats = 65536 (w2t then difft)
#define SM_TOTAL 163840

// ---- packed f32x2 helpers ----
__device__ __forceinline__ u64 pk2(float x) {
    u64 r; asm("mov.b64 %0, {%1, %1};" : "=l"(r) : "f"(x)); return r;
}
__device__ __forceinline__ void fma2(u64& d, u64 a, u64 b) {
    asm("fma.rn.f32x2 %0, %1, %2, %0;" : "+l"(d) : "l"(a), "l"(b));
}
__device__ __forceinline__ float2 up(u64 v) {
    float2 f; asm("mov.b64 {%0, %1}, %2;" : "=f"(f.x), "=f"(f.y) : "l"(v)); return f;
}

// ---- init1: fold conv1 into conv2 (interior composite) ---------------------
__global__ void init1_kernel(const float* __restrict__ w1, const float* __restrict__ b1,
                             const float* __restrict__ w2, const float* __restrict__ b2)
{
    int t = threadIdx.x;
    if (t < 576) {                       // WC[oc][tt], tt = k1+k2 in 0..8
        int oc = t / 9, tt = t % 9;
        float s = 0.f;
        for (int ic = 0; ic < 32; ic++) {
            int klo = tt - 4 > 0 ? tt - 4 : 0;
            int khi = tt < 4 ? tt : 4;
            for (int k = klo; k <= khi; k++)
                s += w2[(oc * 32 + ic) * 5 + k] * w1[ic * 5 + (tt - k)];
        }
        g_WC[t] = s;
    } else if (t < 640) {                // bC[oc]
        int oc = t - 576;
        float s = b2[oc];
        for (int ic = 0; ic < 32; ic++) {
            float ws = 0.f;
            for (int k = 0; k < 5; k++) ws += w2[(oc * 32 + ic) * 5 + k];
            s += b1[ic] * ws;
        }
        g_bC[oc] = s;
    }
}

// ---- init2: fold lin1 into composite; transpose w2, diff -------------------
__global__ void init2_kernel(const float* __restrict__ l1w, const float* __restrict__ l1b,
                             const float* __restrict__ l2w, const float* __restrict__ diff)
{
    int t = blockIdx.x * blockDim.x + threadIdx.x;
    if (t < 576) {                       // we9[jp][tt]
        int jp = t / 9, tt = t % 9;
        float sx = 0.f, sy = 0.f;
        for (int oc = 0; oc < 64; oc++) {
            float wc = g_WC[oc * 9 + tt];
            sx += l1w[(2 * jp)     * 64 + oc] * wc;
            sy += l1w[(2 * jp + 1) * 64 + oc] * wc;
        }
        g_we9[t] = make_float2(sx, sy);
    } else if (t < 640) {                // bep[jp]
        int jp = t - 576;
        float sx = l1b[2 * jp], sy = l1b[2 * jp + 1];
        for (int oc = 0; oc < 64; oc++) {
            float bc = g_bC[oc];
            sx += l1w[(2 * jp)     * 64 + oc] * bc;
            sy += l1w[(2 * jp + 1) * 64 + oc] * bc;
        }
        g_bep[jp] = make_float2(sx, sy);
    }
    if (t >= 1024 && t < 1024 + 128 * 128) {   // w2t
        int idx = t - 1024;
        int j = idx >> 7, k = idx & 127;
        int h = (j >> 2) & 1, txw = j >> 3, jj = j & 3;
        g_w2t[(k * 2 + h) * 64 + txw * 4 + jj] = l2w[j * 128 + k];
    }
    if (t >= 17408 && t < 17408 + 64 * 128) {  // difft
        int idx = t - 17408;
        int a = idx >> 7, k = idx & 127;
        g_difft[k * 64 + a] = diff[a * 128 + k];
    }
}

// ---- init3: exact boundary h1 columns (l = 0,1,L-2,L-1) per b --------------
__global__ void boundary_kernel(const float* __restrict__ binc,
                                const float* __restrict__ w1, const float* __restrict__ b1,
                                const float* __restrict__ w2, const float* __restrict__ b2,
                                const float* __restrict__ l1w, const float* __restrict__ l1b)
{
    __shared__ float c1L[32][4], c1R[32][4];
    __shared__ float c2b[4][64];
    __shared__ float xL[8], xR[8];
    int b = blockIdx.x, t = threadIdx.x;
    const float* x = binc + b * L_;
    if (t < 6)             xL[t]     = x[t];              // x[0..5]
    if (t >= 8 && t < 14)  xR[t - 8] = x[L_ - 6 + t - 8]; // x[L-6..L-1]
    __syncthreads();
    {   // c1 at left p=0..3 (pos p) and right p=0..3 (pos L-4+p), x zero-padded
        int ic = t >> 2, p = t & 3;
        float aL = b1[ic], aR = b1[ic];
        #pragma unroll
        for (int k = 0; k < 5; k++) {
            float w = w1[ic * 5 + k];
            int qL = p + k - 2;              // x index (left)
            if (qL >= 0) aL += w * xL[qL];   // qL <= 5 always
            int qR = p + k;                  // xR index: pos L-6+(p+k)
            if (qR < 6) aR += w * xR[qR];
        }
        c1L[ic][p] = aL; c1R[ic][p] = aR;
    }
    __syncthreads();
    {   // c2 at the 4 boundary columns, with conv1-output masking
        int oc = t & 63, li0 = t >> 6;       // li0 in {0,1}
        #pragma unroll
        for (int e = 0; e < 2; e++) {
            int li = li0 + 2 * e;            // 0,1 -> l=0,1 ; 2,3 -> l=L-2,L-1
            float acc = b2[oc];
            for (int ic = 0; ic < 32; ic++) {
                const float* wr = &w2[(oc * 32 + ic) * 5];
                if (li == 0) {      // pos = k-2 >= 0 -> k>=2, c1L[k-2]
                    #pragma unroll
                    for (int k = 2; k < 5; k++) acc += wr[k] * c1L[ic][k - 2];
                } else if (li == 1) { // pos = k-1 >= 0 -> k>=1
                    #pragma unroll
                    for (int k = 1; k < 5; k++) acc += wr[k] * c1L[ic][k - 1];
                } else if (li == 2) { // l=L-2: pos=L-4+k < L -> k<4, c1R[k]
                    #pragma unroll
                    for (int k = 0; k < 4; k++) acc += wr[k] * c1R[ic][k];
                } else {            // l=L-1: pos=L-3+k < L -> k<3, c1R[k+1]
                    #pragma unroll
                    for (int k = 0; k < 3; k++) acc += wr[k] * c1R[ic][k + 1];
                }
            }
            c2b[li][oc] = acc;
        }
    }
    __syncthreads();
    {   // h1 = relu(lin1(c2)) for the 4 columns
        int j = t;
        #pragma unroll
        for (int li = 0; li < 4; li++) {
            float h = l1b[j];
            for (int oc = 0; oc < 64; oc++) h += l1w[j * 64 + oc] * c2b[li][oc];
            g_hsb[b * 512 + li * 128 + j] = fmaxf(h, 0.f);
        }
    }
}

__global__ void __launch_bounds__(NTHR, 1)
fused_kernel(const float* __restrict__ binc_g,
             const float* __restrict__ l2b_g,
             const float* __restrict__ baseline_g,
             const int*   __restrict__ regions_oi_g)
{
    extern __shared__ char smem[];
    float* sbinc = (float*)(smem + SM_BINC);
    u64*   swe   = (u64*)(smem + SM_WE9);
    u64*   sbep  = (u64*)(smem + SM_BEP);
    float* red   = (float*)(smem + SM_RED);
    float* bm    = (float*)(smem + SM_BM);
    float* hs    = (float*)(smem + SM_HS);     // [128][128] (feat, l); h1 then h2
    float* wbuf  = (float*)(smem + SM_WBUF);   // w2t then difft

    const int t       = threadIdx.x;
    const int tileIdx = blockIdx.x;
    const int b       = blockIdx.y;
    const int l0      = tileIdx * TILE;

    // ---- coalesced staging: w2t -> wbuf, we9/bep, bincounts halo ----
    {
        const float4* s = (const float4*)g_w2t;
        float4*       d = (float4*)wbuf;
        #pragma unroll
        for (int i = 0; i < 16; i++) d[t + i * NTHR] = s[t + i * NTHR];
    }
    for (int i = t; i < 288; i += NTHR)
        ((float4*)swe)[i] = ((const float4*)g_we9)[i];
    if (t < 32) ((float4*)sbep)[t] = ((const float4*)g_bep)[t];
    if (t < TILE + 8) {
        int l = l0 - 4 + t;
        sbinc[t] = (l >= 0 && l < L_) ? binc_g[b * L_ + l] : 0.f;
    }
    __syncthreads();

    // ---- composite conv9: hs[j][l] = relu(bE[j] + sum_t WE[j][t]*x[l+t-4]) ----
    for (int item = t; item < 64 * 16; item += NTHR) {
        int jp = item >> 4;
        int lb = (item & 15) * 8;
        u64 binit = sbep[jp];
        u64 acc[8];
        #pragma unroll
        for (int i = 0; i < 8; i++) acc[i] = binit;
        float xs[16];
        #pragma unroll
        for (int q = 0; q < 4; q++) {
            float4 v = *(const float4*)&sbinc[lb + q * 4];
            xs[q * 4] = v.x; xs[q * 4 + 1] = v.y; xs[q * 4 + 2] = v.z; xs[q * 4 + 3] = v.w;
        }
        u64 xv[16];
        #pragma unroll
        for (int i = 0; i < 16; i++) xv[i] = pk2(xs[i]);
        const u64* wp = &swe[jp * 9];
        #pragma unroll
        for (int k = 0; k < 9; k++) {
            u64 w = wp[k];
            #pragma unroll
            for (int i = 0; i < 8; i++) fma2(acc[i], xv[i + k], w);
        }
        float r0[8], r1[8];
        #pragma unroll
        for (int i = 0; i < 8; i++) {
            float2 v = up(acc[i]);
            r0[i] = fmaxf(v.x, 0.f); r1[i] = fmaxf(v.y, 0.f);
        }
        *(float4*)&hs[(2 * jp)     * 128 + lb]     = make_float4(r0[0], r0[1], r0[2], r0[3]);
        *(float4*)&hs[(2 * jp)     * 128 + lb + 4] = make_float4(r0[4], r0[5], r0[6], r0[7]);
        *(float4*)&hs[(2 * jp + 1) * 128 + lb]     = make_float4(r1[0], r1[1], r1[2], r1[3]);
        *(float4*)&hs[(2 * jp + 1) * 128 + lb + 4] = make_float4(r1[4], r1[5], r1[6], r1[7]);
    }
    // exact boundary columns override (l = 0,1 and L-2,L-1)
    if (tileIdx == 0) {
        __syncthreads();
        int li = t >> 7, j = t & 127;
        hs[j * 128 + li] = g_hsb[b * 512 + li * 128 + j];
    } else if (tileIdx == NTILE - 1) {
        __syncthreads();
        int li = t >> 7, j = t & 127;       // l = 1998,1999 -> local 78,79
        hs[j * 128 + 78 + li] = g_hsb[b * 512 + (2 + li) * 128 + j];
    }
    __syncthreads();

    // ---- register-tiled GEMMs: 16x16 threads, 8x8 tiles, j-packed ----
    const int tx = t & 15, ty = t >> 4;
    const int row0 = ty * 8;
    const int col0 = tx * 8;

    // GEMM2 (K=128): h2 = relu(h1^T w2^T + b2)
    u64 accB[8][4];
    #pragma unroll
    for (int i = 0; i < 8; i++)
        #pragma unroll
        for (int p = 0; p < 4; p++) accB[i][p] = 0ull;
    for (int k = 0; k < 128; k++) {
        float4 a0 = *(const float4*)&hs[k * 128 + row0];
        float4 a1 = *(const float4*)&hs[k * 128 + row0 + 4];
        u64 av2[8] = {pk2(a0.x), pk2(a0.y), pk2(a0.z), pk2(a0.w),
                      pk2(a1.x), pk2(a1.y), pk2(a1.z), pk2(a1.w)};
        ulonglong2 B0 = *(const ulonglong2*)&wbuf[(k * 2 + 0) * 64 + tx * 4];
        ulonglong2 B1 = *(const ulonglong2*)&wbuf[(k * 2 + 1) * 64 + tx * 4];
        u64 bv2[4] = {B0.x, B0.y, B1.x, B1.y};
        #pragma unroll
        for (int i = 0; i < 8; i++)
            #pragma unroll
            for (int p = 0; p < 4; p++) fma2(accB[i][p], av2[i], bv2[p]);
    }
    __syncthreads();

    {
        #pragma unroll
        for (int p = 0; p < 4; p++) {
            float bx = l2b_g[col0 + 2 * p];
            float by = l2b_g[col0 + 2 * p + 1];
            #pragma unroll
            for (int i = 0; i < 8; i++) {
                float2 v = up(accB[i][p]);
                hs[(col0 + 2 * p)     * 128 + row0 + i] = fmaxf(v.x + bx, 0.f);
                hs[(col0 + 2 * p + 1) * 128 + row0 + i] = fmaxf(v.y + by, 0.f);
            }
        }
    }
    {
        const float4* s = (const float4*)g_difft;
        float4*       d = (float4*)wbuf;
        #pragma unroll
        for (int i = 0; i < 8; i++) d[t + i * NTHR] = s[t + i * NTHR];
    }
    __syncthreads();

    // GEMM3 (K=128, N=64): u = h2^T diff^T + baseline
    const int col3 = tx * 4;
    u64 accC[8][2];
    #pragma unroll
    for (int i = 0; i < 8; i++)
        #pragma unroll
        for (int p = 0; p < 2; p++) accC[i][p] = 0ull;
    for (int k = 0; k < 128; k++) {
        float4 a0 = *(const float4*)&hs[k * 128 + row0];
        float4 a1 = *(const float4*)&hs[k * 128 + row0 + 4];
        u64 av2[8] = {pk2(a0.x), pk2(a0.y), pk2(a0.z), pk2(a0.w),
                      pk2(a1.x), pk2(a1.y), pk2(a1.z), pk2(a1.w)};
        ulonglong2 B0 = *(const ulonglong2*)&wbuf[k * 64 + tx * 4];
        u64 bv2[2] = {B0.x, B0.y};
        #pragma unroll
        for (int i = 0; i < 8; i++)
            #pragma unroll
            for (int p = 0; p < 2; p++) fma2(accC[i][p], av2[i], bv2[p]);
    }

    // epilogue: add baseline, write u, per-tile logsumexp partials
    const int r = regions_oi_g[b];
    float bval[8];
    bool  valid[8];
    #pragma unroll
    for (int i = 0; i < 8; i++) {
        int gl = l0 + row0 + i;
        valid[i] = (gl < L_);
        bval[i]  = valid[i] ? baseline_g[r * L_ + gl] : 0.f;
    }
    float uv[8][4];
    #pragma unroll
    for (int i = 0; i < 8; i++) {
        #pragma unroll
        for (int p = 0; p < 2; p++) {
            float2 v = up(accC[i][p]);
            uv[i][2 * p]     = v.x + bval[i];
            uv[i][2 * p + 1] = v.y + bval[i];
        }
    }
    float mloc[4] = {-FLT_MAX, -FLT_MAX, -FLT_MAX, -FLT_MAX};
    #pragma unroll
    for (int i = 0; i < 8; i++) {
        if (!valid[i]) continue;
        int gl = l0 + row0 + i;
        *(float4*)&g_U[(size_t)(b * L_ + gl) * A_ + col3] =
            make_float4(uv[i][0], uv[i][1], uv[i][2], uv[i][3]);
        #pragma unroll
        for (int j = 0; j < 4; j++) mloc[j] = fmaxf(mloc[j], uv[i][j]);
    }
    #pragma unroll
    for (int j = 0; j < 4; j++) red[ty * 64 + col3 + j] = mloc[j];
    __syncthreads();
    if (t < 64) {
        float m = -FLT_MAX;
        #pragma unroll
        for (int q = 0; q < 16; q++) m = fmaxf(m, red[q * 64 + t]);
        bm[t] = m;
    }
    __syncthreads();
    float bmj[4];
    #pragma unroll
    for (int j = 0; j < 4; j++) bmj[j] = bm[col3 + j];
    float sloc[4] = {0.f, 0.f, 0.f, 0.f};
    #pragma unroll
    for (int i = 0; i < 8; i++) {
        if (!valid[i]) continue;
        #pragma unroll
        for (int j = 0; j < 4; j++) sloc[j] += __expf(uv[i][j] - bmj[j]);
    }
    #pragma unroll
    for (int j = 0; j < 4; j++) red[ty * 64 + col3 + j] = sloc[j];
    __syncthreads();
    if (t < 64) {
        float s = 0.f;
        #pragma unroll
        for (int q = 0; q < 16; q++) s += red[q * 64 + t];
        g_pmax[(b * NTILE + tileIdx) * A_ + t] = bm[t];
        g_psum[(b * NTILE + tileIdx) * A_ + t] = s;
    }
}

__global__ void combine_kernel()
{
    int id = blockIdx.x * blockDim.x + threadIdx.x;
    if (id >= B_ * A_) return;
    int b = id >> 6, a = id & 63;
    float m = -FLT_MAX;
    #pragma unroll
    for (int q = 0; q < NTILE; q++)
        m = fmaxf(m, g_pmax[(b * NTILE + q) * A_ + a]);
    float s = 0.f;
    #pragma unroll
    for (int q = 0; q < NTILE; q++)
        s += g_psum[(b * NTILE + q) * A_ + a] * __expf(g_pmax[(b * NTILE + q) * A_ + a] - m);
    g_logZ[b * A_ + a] = m + logf(s);
}

__global__ void gather_kernel(const int* __restrict__ labels,
                              const int* __restrict__ cell_ix,
                              const int* __restrict__ region_ix,
                              const int* __restrict__ binixs,
                              float* __restrict__ out, int nf)
{
    int f = blockIdx.x * blockDim.x + threadIdx.x;
    if (f >= nf) return;
    int a = labels[cell_ix[f]];
    int b = region_ix[f];
    int l = binixs[f];
    out[f] = g_U[(size_t)(b * L_ + l) * A_ + a] - g_logZ[b * A_ + a]
           + 5.545177444479562f;  // + log(B=256)
}

extern "C" void kernel_launch(void* const* d_in, const int* in_sizes, int n_in,
                              void* d_out, int out_size)
{
    const float* bincounts  = (const float*)d_in[0];
    const float* conv1_w    = (const float*)d_in[1];
    const float* conv1_b    = (const float*)d_in[2];
    const float* conv2_w    = (const float*)d_in[3];
    const float* conv2_b    = (const float*)d_in[4];
    const float* lin1_w     = (const float*)d_in[5];
    const float* lin1_b     = (const float*)d_in[6];
    const float* lin2_w     = (const float*)d_in[7];
    const float* lin2_b     = (const float*)d_in[8];
    const float* baseline   = (const float*)d_in[9];
    const float* diff       = (const float*)d_in[10];
    const int*   regions_oi = (const int*)d_in[11];
    const int*   labels     = (const int*)d_in[12];
    const int*   cell_ix    = (const int*)d_in[13];
    const int*   region_ix  = (const int*)d_in[14];
    const int*   binixs     = (const int*)d_in[15];
    float* out = (float*)d_out;
    int nf = in_sizes[13];

    cudaFuncSetAttribute(fused_kernel,
                         cudaFuncAttributeMaxDynamicSharedMemorySize, SM_TOTAL);

    init1_kernel<<<1, 640>>>(conv1_w, conv1_b, conv2_w, conv2_b);
    init2_kernel<<<100, 256>>>(lin1_w, lin1_b, lin2_w, diff);
    boundary_kernel<<<B_, 128>>>(bincounts, conv1_w, conv1_b, conv2_w, conv2_b,
                                 lin1_w, lin1_b);

    dim3 grid(NTILE, B_);
    fused_kernel<<<grid, NTHR, SM_TOTAL>>>(bincounts, lin2_b, baseline, regions_oi);
    combine_kernel<<<(B_ * A_ + 255) / 256, 256>>>();
    gather_kernel<<<(nf + 255) / 256, 256>>>(labels, cell_ix, region_ix,
                                             binixs, out, nf);
}

// round 8
// speedup vs baseline: 2.5347x; 1.0263x over previous
#include <cuda_runtime.h>
#include <float.h>
#include <math.h>

#define A_  64
#define B_  256
#define L_  2000
#define FC1 32
#define FC2 64
#define H_  128
#define KK  5
#define TILE 128
#define NTILE 16   // 16*128 = 2048 >= 2000
#define NTHR 256

typedef unsigned long long u64;

// ---------------- scratch (device globals; no allocation allowed) ----------
__device__ float g_U[B_ * L_ * A_];          // u[b][l][a], 131 MB
__device__ float g_pmax[B_ * NTILE * A_];
__device__ float g_psum[B_ * NTILE * A_];
__device__ float g_logZ[B_ * A_];

// folded weights (filled by init kernels each launch)
__device__ float  g_WC[64 * 9];          // conv2∘conv1 composite [oc][t], t=k1+k2
__device__ float  g_bC[64];              // composite conv bias (interior)
__device__ float2 g_we9[64 * 9];         // lin1∘conv composite, jp-paired
__device__ float2 g_bep[64];             // folded bias pairs
__device__ float  g_w2t[128 * 128];      // [(k*2+h)*64 + txw*4 + jj] = w2[j][k]
__device__ float  g_difft[128 * 64];     // [k*64 + a] = diff[a][k]
__device__ float  g_hsb[B_ * 4 * 128];   // exact boundary h1 (relu'd)

// ---------------- shared memory layout (bytes) ------------------------------
#define SM_BINC  0                 // 144 floats (576 B)
#define SM_WE9   576               // u64[576] = 4608 B
#define SM_BEP   5184              // float2[64] = 512 B
#define SM_RED   5696              // float[16][64] = 4096 B
#define SM_BM    9792              // float[64] = 256 B
#define SM_HS    32768             // float[128][128] = 65536
#define SM_WBUF  98304             // 16384 floats = 65536 (w2t)
#define SM_DIFF  163840            // 8192 floats = 32768 (difft)
#define SM_TOTAL 196608

// ---- packed f32x2 helpers ----
__device__ __forceinline__ u64 pk2(float x) {
    u64 r; asm("mov.b64 %0, {%1, %1};" : "=l"(r) : "f"(x)); return r;
}
__device__ __forceinline__ void fma2(u64& d, u64 a, u64 b) {
    asm("fma.rn.f32x2 %0, %1, %2, %0;" : "+l"(d) : "l"(a), "l"(b));
}
__device__ __forceinline__ float2 up(u64 v) {
    float2 f; asm("mov.b64 {%0, %1}, %2;" : "=f"(f.x), "=f"(f.y) : "l"(v)); return f;
}

// ---- init1: fold conv1 into conv2 (interior composite) ---------------------
__global__ void init1_kernel(const float* __restrict__ w1, const float* __restrict__ b1,
                             const float* __restrict__ w2, const float* __restrict__ b2)
{
    int t = threadIdx.x;
    if (t < 576) {
        int oc = t / 9, tt = t % 9;
        float s = 0.f;
        for (int ic = 0; ic < 32; ic++) {
            int klo = tt - 4 > 0 ? tt - 4 : 0;
            int khi = tt < 4 ? tt : 4;
            for (int k = klo; k <= khi; k++)
                s += w2[(oc * 32 + ic) * 5 + k] * w1[ic * 5 + (tt - k)];
        }
        g_WC[t] = s;
    } else if (t < 640) {
        int oc = t - 576;
        float s = b2[oc];
        for (int ic = 0; ic < 32; ic++) {
            float ws = 0.f;
            for (int k = 0; k < 5; k++) ws += w2[(oc * 32 + ic) * 5 + k];
            s += b1[ic] * ws;
        }
        g_bC[oc] = s;
    }
}

// ---- init2: fold lin1 into composite; transpose w2, diff -------------------
__global__ void init2_kernel(const float* __restrict__ l1w, const float* __restrict__ l1b,
                             const float* __restrict__ l2w, const float* __restrict__ diff)
{
    int t = blockIdx.x * blockDim.x + threadIdx.x;
    if (t < 576) {
        int jp = t / 9, tt = t % 9;
        float sx = 0.f, sy = 0.f;
        for (int oc = 0; oc < 64; oc++) {
            float wc = g_WC[oc * 9 + tt];
            sx += l1w[(2 * jp)     * 64 + oc] * wc;
            sy += l1w[(2 * jp + 1) * 64 + oc] * wc;
        }
        g_we9[t] = make_float2(sx, sy);
    } else if (t < 640) {
        int jp = t - 576;
        float sx = l1b[2 * jp], sy = l1b[2 * jp + 1];
        for (int oc = 0; oc < 64; oc++) {
            float bc = g_bC[oc];
            sx += l1w[(2 * jp)     * 64 + oc] * bc;
            sy += l1w[(2 * jp + 1) * 64 + oc] * bc;
        }
        g_bep[jp] = make_float2(sx, sy);
    }
    if (t >= 1024 && t < 1024 + 128 * 128) {   // w2t
        int idx = t - 1024;
        int j = idx >> 7, k = idx & 127;
        int h = (j >> 2) & 1, txw = j >> 3, jj = j & 3;
        g_w2t[(k * 2 + h) * 64 + txw * 4 + jj] = l2w[j * 128 + k];
    }
    if (t >= 17408 && t < 17408 + 64 * 128) {  // difft
        int idx = t - 17408;
        int a = idx >> 7, k = idx & 127;
        g_difft[k * 64 + a] = diff[a * 128 + k];
    }
}

// ---- init3: exact boundary h1 columns (l = 0,1,L-2,L-1) per b --------------
__global__ void boundary_kernel(const float* __restrict__ binc,
                                const float* __restrict__ w1, const float* __restrict__ b1,
                                const float* __restrict__ w2, const float* __restrict__ b2,
                                const float* __restrict__ l1w, const float* __restrict__ l1b)
{
    __shared__ float c1L[32][4], c1R[32][4];
    __shared__ float c2b[4][64];
    __shared__ float xL[8], xR[8];
    int b = blockIdx.x, t = threadIdx.x;
    const float* x = binc + b * L_;
    if (t < 6)             xL[t]     = x[t];
    if (t >= 8 && t < 14)  xR[t - 8] = x[L_ - 6 + t - 8];
    __syncthreads();
    {
        int ic = t >> 2, p = t & 3;
        float aL = b1[ic], aR = b1[ic];
        #pragma unroll
        for (int k = 0; k < 5; k++) {
            float w = w1[ic * 5 + k];
            int qL = p + k - 2;
            if (qL >= 0) aL += w * xL[qL];
            int qR = p + k;
            if (qR < 6) aR += w * xR[qR];
        }
        c1L[ic][p] = aL; c1R[ic][p] = aR;
    }
    __syncthreads();
    {
        int oc = t & 63, li0 = t >> 6;
        #pragma unroll
        for (int e = 0; e < 2; e++) {
            int li = li0 + 2 * e;
            float acc = b2[oc];
            for (int ic = 0; ic < 32; ic++) {
                const float* wr = &w2[(oc * 32 + ic) * 5];
                if (li == 0) {
                    #pragma unroll
                    for (int k = 2; k < 5; k++) acc += wr[k] * c1L[ic][k - 2];
                } else if (li == 1) {
                    #pragma unroll
                    for (int k = 1; k < 5; k++) acc += wr[k] * c1L[ic][k - 1];
                } else if (li == 2) {
                    #pragma unroll
                    for (int k = 0; k < 4; k++) acc += wr[k] * c1R[ic][k];
                } else {
                    #pragma unroll
                    for (int k = 0; k < 3; k++) acc += wr[k] * c1R[ic][k + 1];
                }
            }
            c2b[li][oc] = acc;
        }
    }
    __syncthreads();
    {
        int j = t;
        #pragma unroll
        for (int li = 0; li < 4; li++) {
            float h = l1b[j];
            for (int oc = 0; oc < 64; oc++) h += l1w[j * 64 + oc] * c2b[li][oc];
            g_hsb[b * 512 + li * 128 + j] = fmaxf(h, 0.f);
        }
    }
}

__global__ void __launch_bounds__(NTHR, 1)
fused_kernel(const float* __restrict__ binc_g,
             const float* __restrict__ l2b_g,
             const float* __restrict__ baseline_g,
             const int*   __restrict__ regions_oi_g)
{
    extern __shared__ char smem[];
    float* sbinc = (float*)(smem + SM_BINC);
    u64*   swe   = (u64*)(smem + SM_WE9);
    u64*   sbep  = (u64*)(smem + SM_BEP);
    float* red   = (float*)(smem + SM_RED);
    float* bm    = (float*)(smem + SM_BM);
    float* hs    = (float*)(smem + SM_HS);     // [128][128]; h1 then h2
    float* wbuf  = (float*)(smem + SM_WBUF);   // w2t
    float* sdiff = (float*)(smem + SM_DIFF);   // difft

    const int t       = threadIdx.x;
    const int tileIdx = blockIdx.x;
    const int b       = blockIdx.y;
    const int l0      = tileIdx * TILE;

    // ---- coalesced staging: w2t, difft, we9/bep, bincounts halo ----
    {
        const float4* s = (const float4*)g_w2t;
        float4*       d = (float4*)wbuf;
        #pragma unroll
        for (int i = 0; i < 16; i++) d[t + i * NTHR] = s[t + i * NTHR];
        const float4* s2 = (const float4*)g_difft;
        float4*       d2 = (float4*)sdiff;
        #pragma unroll
        for (int i = 0; i < 8; i++) d2[t + i * NTHR] = s2[t + i * NTHR];
    }
    for (int i = t; i < 288; i += NTHR)
        ((float4*)swe)[i] = ((const float4*)g_we9)[i];
    if (t < 32) ((float4*)sbep)[t] = ((const float4*)g_bep)[t];
    if (t < TILE + 8) {
        int l = l0 - 4 + t;
        sbinc[t] = (l >= 0 && l < L_) ? binc_g[b * L_ + l] : 0.f;
    }
    __syncthreads();

    // ---- composite conv9: hs[j][l] = relu(bE[j] + sum_t WE[j][t]*x[l+t-4]) ----
    for (int item = t; item < 64 * 16; item += NTHR) {
        int jp = item >> 4;
        int lb = (item & 15) * 8;
        u64 binit = sbep[jp];
        u64 acc[8];
        #pragma unroll
        for (int i = 0; i < 8; i++) acc[i] = binit;
        float xs[16];
        #pragma unroll
        for (int q = 0; q < 4; q++) {
            float4 v = *(const float4*)&sbinc[lb + q * 4];
            xs[q * 4] = v.x; xs[q * 4 + 1] = v.y; xs[q * 4 + 2] = v.z; xs[q * 4 + 3] = v.w;
        }
        u64 xv[16];
        #pragma unroll
        for (int i = 0; i < 16; i++) xv[i] = pk2(xs[i]);
        const u64* wp = &swe[jp * 9];
        #pragma unroll
        for (int k = 0; k < 9; k++) {
            u64 w = wp[k];
            #pragma unroll
            for (int i = 0; i < 8; i++) fma2(acc[i], xv[i + k], w);
        }
        float r0[8], r1[8];
        #pragma unroll
        for (int i = 0; i < 8; i++) {
            float2 v = up(acc[i]);
            r0[i] = fmaxf(v.x, 0.f); r1[i] = fmaxf(v.y, 0.f);
        }
        *(float4*)&hs[(2 * jp)     * 128 + lb]     = make_float4(r0[0], r0[1], r0[2], r0[3]);
        *(float4*)&hs[(2 * jp)     * 128 + lb + 4] = make_float4(r0[4], r0[5], r0[6], r0[7]);
        *(float4*)&hs[(2 * jp + 1) * 128 + lb]     = make_float4(r1[0], r1[1], r1[2], r1[3]);
        *(float4*)&hs[(2 * jp + 1) * 128 + lb + 4] = make_float4(r1[4], r1[5], r1[6], r1[7]);
    }
    // exact boundary columns override (l = 0,1 and L-2,L-1)
    if (tileIdx == 0) {
        __syncthreads();
        int li = t >> 7, j = t & 127;
        hs[j * 128 + li] = g_hsb[b * 512 + li * 128 + j];
    } else if (tileIdx == NTILE - 1) {
        __syncthreads();
        int li = t >> 7, j = t & 127;       // l = 1998,1999 -> local 78,79
        hs[j * 128 + 78 + li] = g_hsb[b * 512 + (2 + li) * 128 + j];
    }
    __syncthreads();

    // ---- register-tiled GEMMs: 16x16 threads, 8x8 tiles, j-packed ----
    const int tx = t & 15, ty = t >> 4;
    const int row0 = ty * 8;
    const int col0 = tx * 8;

    // GEMM2 (K=128): h2 = relu(h1^T w2^T + b2) — software-pipelined
    u64 accB[8][4];
    #pragma unroll
    for (int i = 0; i < 8; i++)
        #pragma unroll
        for (int p = 0; p < 4; p++) accB[i][p] = 0ull;
    {
        float4 a0 = *(const float4*)&hs[row0];
        float4 a1 = *(const float4*)&hs[row0 + 4];
        ulonglong2 B0 = *(const ulonglong2*)&wbuf[tx * 4];
        ulonglong2 B1 = *(const ulonglong2*)&wbuf[64 + tx * 4];
        #pragma unroll 4
        for (int k = 0; k < 128; k++) {
            float4 ca0 = a0, ca1 = a1;
            ulonglong2 cB0 = B0, cB1 = B1;
            int kn = k < 127 ? k + 1 : 127;
            a0 = *(const float4*)&hs[kn * 128 + row0];
            a1 = *(const float4*)&hs[kn * 128 + row0 + 4];
            B0 = *(const ulonglong2*)&wbuf[(kn * 2 + 0) * 64 + tx * 4];
            B1 = *(const ulonglong2*)&wbuf[(kn * 2 + 1) * 64 + tx * 4];
            u64 av2[8] = {pk2(ca0.x), pk2(ca0.y), pk2(ca0.z), pk2(ca0.w),
                          pk2(ca1.x), pk2(ca1.y), pk2(ca1.z), pk2(ca1.w)};
            u64 bv2[4] = {cB0.x, cB0.y, cB1.x, cB1.y};
            #pragma unroll
            for (int i = 0; i < 8; i++)
                #pragma unroll
                for (int p = 0; p < 4; p++) fma2(accB[i][p], av2[i], bv2[p]);
        }
    }
    __syncthreads();

    {
        #pragma unroll
        for (int p = 0; p < 4; p++) {
            float bx = l2b_g[col0 + 2 * p];
            float by = l2b_g[col0 + 2 * p + 1];
            #pragma unroll
            for (int i = 0; i < 8; i++) {
                float2 v = up(accB[i][p]);
                hs[(col0 + 2 * p)     * 128 + row0 + i] = fmaxf(v.x + bx, 0.f);
                hs[(col0 + 2 * p + 1) * 128 + row0 + i] = fmaxf(v.y + by, 0.f);
            }
        }
    }
    __syncthreads();

    // GEMM3 (K=128, N=64): u = h2^T diff^T + baseline — software-pipelined
    const int col3 = tx * 4;
    u64 accC[8][2];
    #pragma unroll
    for (int i = 0; i < 8; i++)
        #pragma unroll
        for (int p = 0; p < 2; p++) accC[i][p] = 0ull;
    {
        float4 a0 = *(const float4*)&hs[row0];
        float4 a1 = *(const float4*)&hs[row0 + 4];
        ulonglong2 B0 = *(const ulonglong2*)&sdiff[tx * 4];
        #pragma unroll 4
        for (int k = 0; k < 128; k++) {
            float4 ca0 = a0, ca1 = a1;
            ulonglong2 cB0 = B0;
            int kn = k < 127 ? k + 1 : 127;
            a0 = *(const float4*)&hs[kn * 128 + row0];
            a1 = *(const float4*)&hs[kn * 128 + row0 + 4];
            B0 = *(const ulonglong2*)&sdiff[kn * 64 + tx * 4];
            u64 av2[8] = {pk2(ca0.x), pk2(ca0.y), pk2(ca0.z), pk2(ca0.w),
                          pk2(ca1.x), pk2(ca1.y), pk2(ca1.z), pk2(ca1.w)};
            u64 bv2[2] = {cB0.x, cB0.y};
            #pragma unroll
            for (int i = 0; i < 8; i++)
                #pragma unroll
                for (int p = 0; p < 2; p++) fma2(accC[i][p], av2[i], bv2[p]);
        }
    }

    // epilogue: add baseline, write u, per-tile logsumexp partials
    const int r = regions_oi_g[b];
    float bval[8];
    bool  valid[8];
    #pragma unroll
    for (int i = 0; i < 8; i++) {
        int gl = l0 + row0 + i;
        valid[i] = (gl < L_);
        bval[i]  = valid[i] ? baseline_g[r * L_ + gl] : 0.f;
    }
    float uv[8][4];
    #pragma unroll
    for (int i = 0; i < 8; i++) {
        #pragma unroll
        for (int p = 0; p < 2; p++) {
            float2 v = up(accC[i][p]);
            uv[i][2 * p]     = v.x + bval[i];
            uv[i][2 * p + 1] = v.y + bval[i];
        }
    }
    float mloc[4] = {-FLT_MAX, -FLT_MAX, -FLT_MAX, -FLT_MAX};
    #pragma unroll
    for (int i = 0; i < 8; i++) {
        if (!valid[i]) continue;
        int gl = l0 + row0 + i;
        *(float4*)&g_U[(size_t)(b * L_ + gl) * A_ + col3] =
            make_float4(uv[i][0], uv[i][1], uv[i][2], uv[i][3]);
        #pragma unroll
        for (int j = 0; j < 4; j++) mloc[j] = fmaxf(mloc[j], uv[i][j]);
    }
    #pragma unroll
    for (int j = 0; j < 4; j++) red[ty * 64 + col3 + j] = mloc[j];
    __syncthreads();
    if (t < 64) {
        float m = -FLT_MAX;
        #pragma unroll
        for (int q = 0; q < 16; q++) m = fmaxf(m, red[q * 64 + t]);
        bm[t] = m;
    }
    __syncthreads();
    float bmj[4];
    #pragma unroll
    for (int j = 0; j < 4; j++) bmj[j] = bm[col3 + j];
    float sloc[4] = {0.f, 0.f, 0.f, 0.f};
    #pragma unroll
    for (int i = 0; i < 8; i++) {
        if (!valid[i]) continue;
        #pragma unroll
        for (int j = 0; j < 4; j++) sloc[j] += __expf(uv[i][j] - bmj[j]);
    }
    #pragma unroll
    for (int j = 0; j < 4; j++) red[ty * 64 + col3 + j] = sloc[j];
    __syncthreads();
    if (t < 64) {
        float s = 0.f;
        #pragma unroll
        for (int q = 0; q < 16; q++) s += red[q * 64 + t];
        g_pmax[(b * NTILE + tileIdx) * A_ + t] = bm[t];
        g_psum[(b * NTILE + tileIdx) * A_ + t] = s;
    }
}

__global__ void combine_kernel()
{
    int id = blockIdx.x * blockDim.x + threadIdx.x;
    if (id >= B_ * A_) return;
    int b = id >> 6, a = id & 63;
    float m = -FLT_MAX;
    #pragma unroll
    for (int q = 0; q < NTILE; q++)
        m = fmaxf(m, g_pmax[(b * NTILE + q) * A_ + a]);
    float s = 0.f;
    #pragma unroll
    for (int q = 0; q < NTILE; q++)
        s += g_psum[(b * NTILE + q) * A_ + a] * __expf(g_pmax[(b * NTILE + q) * A_ + a] - m);
    g_logZ[b * A_ + a] = m + logf(s);
}

__global__ void gather_kernel(const int* __restrict__ labels,
                              const int* __restrict__ cell_ix,
                              const int* __restrict__ region_ix,
                              const int* __restrict__ binixs,
                              float* __restrict__ out, int nf)
{
    int f = blockIdx.x * blockDim.x + threadIdx.x;
    if (f >= nf) return;
    int a = labels[cell_ix[f]];
    int b = region_ix[f];
    int l = binixs[f];
    out[f] = g_U[(size_t)(b * L_ + l) * A_ + a] - g_logZ[b * A_ + a]
           + 5.545177444479562f;  // + log(B=256)
}

extern "C" void kernel_launch(void* const* d_in, const int* in_sizes, int n_in,
                              void* d_out, int out_size)
{
    const float* bincounts  = (const float*)d_in[0];
    const float* conv1_w    = (const float*)d_in[1];
    const float* conv1_b    = (const float*)d_in[2];
    const float* conv2_w    = (const float*)d_in[3];
    const float* conv2_b    = (const float*)d_in[4];
    const float* lin1_w     = (const float*)d_in[5];
    const float* lin1_b     = (const float*)d_in[6];
    const float* lin2_w     = (const float*)d_in[7];
    const float* lin2_b     = (const float*)d_in[8];
    const float* baseline   = (const float*)d_in[9];
    const float* diff       = (const float*)d_in[10];
    const int*   regions_oi = (const int*)d_in[11];
    const int*   labels     = (const int*)d_in[12];
    const int*   cell_ix    = (const int*)d_in[13];
    const int*   region_ix  = (const int*)d_in[14];
    const int*   binixs     = (const int*)d_in[15];
    float* out = (float*)d_out;
    int nf = in_sizes[13];

    cudaFuncSetAttribute(fused_kernel,
                         cudaFuncAttributeMaxDynamicSharedMemorySize, SM_TOTAL);

    init1_kernel<<<1, 640>>>(conv1_w, conv1_b, conv2_w, conv2_b);
    init2_kernel<<<100, 256>>>(lin1_w, lin1_b, lin2_w, diff);
    boundary_kernel<<<B_, 128>>>(bincounts, conv1_w, conv1_b, conv2_w, conv2_b,
                                 lin1_w, lin1_b);

    dim3 grid(NTILE, B_);
    fused_kernel<<<grid, NTHR, SM_TOTAL>>>(bincounts, lin2_b, baseline, regions_oi);
    combine_kernel<<<(B_ * A_ + 255) / 256, 256>>>();
    gather_kernel<<<(nf + 255) / 256, 256>>>(labels, cell_ix, region_ix,
                                             binixs, out, nf);
}